// round 1
// baseline (speedup 1.0000x reference)
#include <cuda_runtime.h>

#define N_NODES 8192
#define F_IN    256
#define F_OUT   64
#define ALPHA   0.2f
#define NEG_BIG -9e15f

// Scratch (allocation-free rule: __device__ globals)
__device__ float g_h[N_NODES * F_OUT];      // 2 MB
__device__ float g_ssrc[N_NODES];
__device__ float g_sdst[N_NODES];

// ---------------------------------------------------------------------------
// Kernel A: h = nodes @ W   (8192x256 @ 256x64)
// 64-row tile per block, BK=64, 4x4 microtile per thread.
// ---------------------------------------------------------------------------
__global__ __launch_bounds__(256) void gemm_h_kernel(
    const float* __restrict__ nodes, const float* __restrict__ W)
{
    __shared__ float As[64][64];   // [r][k]
    __shared__ float Bs[64][64];   // [k][n]

    const int tid = threadIdx.x;
    const int rowBase = blockIdx.x * 64;
    const int tr = tid >> 4;       // 0..15 -> 4 rows each
    const int tc = tid & 15;       // 0..15 -> 4 cols each

    float acc[4][4] = {};

    for (int k0 = 0; k0 < F_IN; k0 += 64) {
        // Load A tile: nodes[rowBase+r][k0+k] -> As[r][k]
#pragma unroll
        for (int it = 0; it < 4; it++) {
            int idx = tid + it * 256;          // float4 index, 0..1023
            int r   = idx >> 4;
            int kq  = (idx & 15) * 4;
            float4 vv = *(const float4*)(nodes + (size_t)(rowBase + r) * F_IN + k0 + kq);
            *(float4*)(&As[r][kq]) = vv;
        }
        // Load B tile: W[k0+k][n] -> Bs[k][n]
#pragma unroll
        for (int it = 0; it < 4; it++) {
            int idx = tid + it * 256;
            int k   = idx >> 4;
            int nq  = (idx & 15) * 4;
            *(float4*)(&Bs[k][nq]) = *(const float4*)(W + (size_t)(k0 + k) * F_OUT + nq);
        }
        __syncthreads();

#pragma unroll
        for (int kk = 0; kk < 64; kk++) {
            float a0 = As[tr * 4 + 0][kk];
            float a1 = As[tr * 4 + 1][kk];
            float a2 = As[tr * 4 + 2][kk];
            float a3 = As[tr * 4 + 3][kk];
            float4 b4 = *(const float4*)(&Bs[kk][tc * 4]);
            acc[0][0] += a0 * b4.x; acc[0][1] += a0 * b4.y; acc[0][2] += a0 * b4.z; acc[0][3] += a0 * b4.w;
            acc[1][0] += a1 * b4.x; acc[1][1] += a1 * b4.y; acc[1][2] += a1 * b4.z; acc[1][3] += a1 * b4.w;
            acc[2][0] += a2 * b4.x; acc[2][1] += a2 * b4.y; acc[2][2] += a2 * b4.z; acc[2][3] += a2 * b4.w;
            acc[3][0] += a3 * b4.x; acc[3][1] += a3 * b4.y; acc[3][2] += a3 * b4.z; acc[3][3] += a3 * b4.w;
        }
        __syncthreads();
    }

#pragma unroll
    for (int rr = 0; rr < 4; rr++) {
        float4 o = make_float4(acc[rr][0], acc[rr][1], acc[rr][2], acc[rr][3]);
        *(float4*)(g_h + (size_t)(rowBase + tr * 4 + rr) * F_OUT + tc * 4) = o;
    }
}

// ---------------------------------------------------------------------------
// Kernel B: s_src[i] = h[i,:] . a[:64],  s_dst[i] = h[i,:] . a[64:]
// warp per row.
// ---------------------------------------------------------------------------
__global__ __launch_bounds__(256) void score_kernel(const float* __restrict__ a)
{
    const int warp = threadIdx.x >> 5;
    const int lane = threadIdx.x & 31;
    const int row  = blockIdx.x * 8 + warp;

    float2 hv = *(const float2*)(g_h + (size_t)row * F_OUT + lane * 2);
    float2 a0 = *(const float2*)(a + lane * 2);
    float2 a1 = *(const float2*)(a + F_OUT + lane * 2);

    float ps = hv.x * a0.x + hv.y * a0.y;
    float pd = hv.x * a1.x + hv.y * a1.y;
#pragma unroll
    for (int o = 16; o; o >>= 1) {
        ps += __shfl_xor_sync(0xffffffffu, ps, o);
        pd += __shfl_xor_sync(0xffffffffu, pd, o);
    }
    if (lane == 0) {
        g_ssrc[row] = ps;
        g_sdst[row] = pd;
    }
}

// ---------------------------------------------------------------------------
// Kernel C: fused masked-softmax attention, warp per row, online softmax with
// underflow skipping. adj streamed once (__ldcs). s_dst staged in smem.
// Lane owns output dims {2*lane, 2*lane+1}.
// ---------------------------------------------------------------------------
__global__ __launch_bounds__(256, 4) void attn_kernel(
    const float* __restrict__ adj, float* __restrict__ out)
{
    __shared__ float sdst_s[N_NODES];   // 32 KB
    for (int t = threadIdx.x; t < N_NODES / 4; t += 256)
        ((float4*)sdst_s)[t] = ((const float4*)g_sdst)[t];
    __syncthreads();

    const int warp = threadIdx.x >> 5;
    const int lane = threadIdx.x & 31;
    const int row  = blockIdx.x * 8 + warp;

    const float ssrc = g_ssrc[row];
    const float* adjrow = adj + (size_t)row * N_NODES;

    const float NEG_INF = __int_as_float(0xff800000);
    float m  = NEG_INF;        // running row max
    float mt = NEG_INF;        // m - 40 (skip threshold)
    float l  = 0.0f;           // per-lane partial sum of p
    float acc0 = 0.0f, acc1 = 0.0f;

    for (int j0 = 0; j0 < N_NODES; j0 += 512) {
        float4 av[4];
#pragma unroll
        for (int u = 0; u < 4; u++)
            av[u] = __ldcs((const float4*)(adjrow + j0 + u * 128) + lane);

#pragma unroll
        for (int u = 0; u < 4; u++) {
            const int jc = j0 + u * 128 + lane * 4;   // this lane's first j
            float4 sd = *(const float4*)(sdst_s + jc);

            float v[4];
            {
                float s, e;
                s = ssrc + sd.x; e = fmaxf(s, ALPHA * s);
                v[0] = (av[u].x > 0.5f) ? e : e * NEG_BIG;
                s = ssrc + sd.y; e = fmaxf(s, ALPHA * s);
                v[1] = (av[u].y > 0.5f) ? e : e * NEG_BIG;
                s = ssrc + sd.z; e = fmaxf(s, ALPHA * s);
                v[2] = (av[u].z > 0.5f) ? e : e * NEG_BIG;
                s = ssrc + sd.w; e = fmaxf(s, ALPHA * s);
                v[3] = (av[u].w > 0.5f) ? e : e * NEG_BIG;
            }
            float cm = fmaxf(fmaxf(v[0], v[1]), fmaxf(v[2], v[3]));

            // Fast path: nothing in this chunk can contribute (>= keeps exact ties)
            if (__any_sync(0xffffffffu, cm >= mt)) {
                float wm = cm;
#pragma unroll
                for (int o = 16; o; o >>= 1)
                    wm = fmaxf(wm, __shfl_xor_sync(0xffffffffu, wm, o));
                if (wm > m) {
                    float sc = __expf(m - wm);   // 0 on first update (m = -inf)
                    l *= sc; acc0 *= sc; acc1 *= sc;
                    m = wm; mt = m - 40.0f;
                }
                float p[4];
#pragma unroll
                for (int k = 0; k < 4; k++) {
                    float d = v[k] - m;
                    p[k] = (d >= -40.0f) ? __expf(d) : 0.0f;
                    l += p[k];
                }
                // Gather the (rare) surviving entries
#pragma unroll
                for (int k = 0; k < 4; k++) {
                    unsigned bm = __ballot_sync(0xffffffffu, p[k] != 0.0f);
                    while (bm) {
                        int b = __ffs(bm) - 1;
                        bm &= bm - 1;
                        float pb = __shfl_sync(0xffffffffu, p[k], b);
                        int j = j0 + u * 128 + b * 4 + k;
                        float2 hv = *(const float2*)(g_h + (size_t)j * F_OUT + lane * 2);
                        acc0 += pb * hv.x;
                        acc1 += pb * hv.y;
                    }
                }
            }
        }
    }

    // Reduce l across the warp (acc stays per-lane: lane owns its 2 dims)
#pragma unroll
    for (int o = 16; o; o >>= 1)
        l += __shfl_xor_sync(0xffffffffu, l, o);

    float inv = 1.0f / l;
    float o0 = acc0 * inv;
    float o1 = acc1 * inv;
    o0 = fmaxf(o0, ALPHA * o0);
    o1 = fmaxf(o1, ALPHA * o1);
    *(float2*)(out + (size_t)row * F_OUT + lane * 2) = make_float2(o0, o1);
}

// ---------------------------------------------------------------------------
extern "C" void kernel_launch(void* const* d_in, const int* in_sizes, int n_in,
                              void* d_out, int out_size)
{
    const float* nodes = (const float*)d_in[0];   // [8192, 256]
    const float* adj   = (const float*)d_in[1];   // [8192, 8192]
    const float* W     = (const float*)d_in[2];   // [256, 64]
    const float* a     = (const float*)d_in[3];   // [128]
    float* out = (float*)d_out;                   // [8192, 64]

    gemm_h_kernel<<<N_NODES / 64, 256>>>(nodes, W);
    score_kernel<<<N_NODES / 8, 256>>>(a);
    attn_kernel<<<N_NODES / 8, 256>>>(adj, out);
}

// round 3
// speedup vs baseline: 2.1449x; 2.1449x over previous
#include <cuda_runtime.h>
#include <math_constants.h>

#define N_NODES 8192
#define F_IN    256
#define F_OUT   64
#define ALPHA   0.2f
#define NEG_BIG -9e15f
#define SAFE_M  1e10f   // ULP(m) >= 1024 >> 88 -> all non-ties underflow to exactly 0

// Scratch (__device__ globals: allocation-free rule)
__device__ float g_h[N_NODES * F_OUT];     // 2 MB
__device__ float g_ssrc[N_NODES];
__device__ float g_sdst[N_NODES];
__device__ float g_m[N_NODES];
__device__ int   g_flag_list[N_NODES];
__device__ int   g_nflag;

// ---------------------------------------------------------------------------
// Kernel A: h = nodes @ W  (8192x256 @ 256x64). 32-row tiles -> 256 blocks.
// ---------------------------------------------------------------------------
__global__ __launch_bounds__(256) void gemm_h_kernel(
    const float* __restrict__ nodes, const float* __restrict__ W)
{
    __shared__ float As[32][68];   // padded: avoid 2-way conflicts
    __shared__ float Bs[64][68];

    const int tid = threadIdx.x;
    const int rowBase = blockIdx.x * 32;
    const int tr = tid >> 4;       // 0..15 -> 2 rows each
    const int tc = tid & 15;       // 0..15 -> 4 cols each

    float acc[2][4] = {};

    for (int k0 = 0; k0 < F_IN; k0 += 64) {
        // A tile: 32x64 = 512 float4, 2 per thread
#pragma unroll
        for (int it = 0; it < 2; it++) {
            int idx = tid + it * 256;
            int r   = idx >> 4;
            int kq  = (idx & 15) * 4;
            float4 vv = *(const float4*)(nodes + (size_t)(rowBase + r) * F_IN + k0 + kq);
            *(float4*)(&As[r][kq]) = vv;
        }
        // B tile: 64x64 = 1024 float4, 4 per thread
#pragma unroll
        for (int it = 0; it < 4; it++) {
            int idx = tid + it * 256;
            int k   = idx >> 4;
            int nq  = (idx & 15) * 4;
            *(float4*)(&Bs[k][nq]) = *(const float4*)(W + (size_t)(k0 + k) * F_OUT + nq);
        }
        __syncthreads();

#pragma unroll
        for (int kk = 0; kk < 64; kk++) {
            float a0 = As[tr * 2 + 0][kk];
            float a1 = As[tr * 2 + 1][kk];
            float4 b4 = *(const float4*)(&Bs[kk][tc * 4]);
            acc[0][0] += a0 * b4.x; acc[0][1] += a0 * b4.y; acc[0][2] += a0 * b4.z; acc[0][3] += a0 * b4.w;
            acc[1][0] += a1 * b4.x; acc[1][1] += a1 * b4.y; acc[1][2] += a1 * b4.z; acc[1][3] += a1 * b4.w;
        }
        __syncthreads();
    }

#pragma unroll
    for (int rr = 0; rr < 2; rr++) {
        float4 o = make_float4(acc[rr][0], acc[rr][1], acc[rr][2], acc[rr][3]);
        *(float4*)(g_h + (size_t)(rowBase + tr * 2 + rr) * F_OUT + tc * 4) = o;
    }
}

// ---------------------------------------------------------------------------
// Kernel B: s_src / s_dst row dots. Warp per row. Also zeroes flag counter.
// ---------------------------------------------------------------------------
__global__ __launch_bounds__(256) void score_kernel(const float* __restrict__ a)
{
    if (blockIdx.x == 0 && threadIdx.x == 0) g_nflag = 0;

    const int warp = threadIdx.x >> 5;
    const int lane = threadIdx.x & 31;
    const int row  = blockIdx.x * 8 + warp;

    float2 hv = *(const float2*)(g_h + (size_t)row * F_OUT + lane * 2);
    float2 a0 = *(const float2*)(a + lane * 2);
    float2 a1 = *(const float2*)(a + F_OUT + lane * 2);

    float ps = hv.x * a0.x + hv.y * a0.y;
    float pd = hv.x * a1.x + hv.y * a1.y;
#pragma unroll
    for (int o = 16; o; o >>= 1) {
        ps += __shfl_xor_sync(0xffffffffu, ps, o);
        pd += __shfl_xor_sync(0xffffffffu, pd, o);
    }
    if (lane == 0) {
        g_ssrc[row] = ps;
        g_sdst[row] = pd;
    }
}

// ---------------------------------------------------------------------------
// Kernel C (pass 1): stream adj once. Running max + exact-tie gather.
// If final m >= SAFE_M: exp(v-m) is exactly {1 for ties, 0 otherwise} in fp32,
// so out = leaky(mean(h over ties)). Else: flag row for dense pass 2.
// Events (new-record or tie chunks) are ~H(#chunks) per row regardless of
// value scale, so the slow path is provably rare.
// ---------------------------------------------------------------------------
__global__ __launch_bounds__(256) void pass1_kernel(
    const float* __restrict__ adj, float* __restrict__ out)
{
    __shared__ float sdst_s[N_NODES];   // 32 KB
    for (int t = threadIdx.x; t < N_NODES / 4; t += 256)
        ((float4*)sdst_s)[t] = ((const float4*)g_sdst)[t];
    __syncthreads();

    const int warp = threadIdx.x >> 5;
    const int lane = threadIdx.x & 31;
    const int row  = blockIdx.x * 8 + warp;

    const float ssrc = g_ssrc[row];
    const float* adjrow = adj + (size_t)row * N_NODES;

    float m = -CUDART_INF_F;
    float cntf = 0.0f;
    float hacc0 = 0.0f, hacc1 = 0.0f;   // lane owns dims 2*lane, 2*lane+1

    for (int j0 = 0; j0 < N_NODES; j0 += 512) {
        float4 av[4];
#pragma unroll
        for (int u = 0; u < 4; u++)
            av[u] = __ldcs((const float4*)(adjrow + j0 + u * 128) + lane);

#pragma unroll
        for (int u = 0; u < 4; u++) {
            const int jc = j0 + u * 128 + lane * 4;
            float4 sd = *(const float4*)(sdst_s + jc);

            float v[4];
            {
                float s, e;
                s = ssrc + sd.x; e = fmaxf(s, ALPHA * s);
                v[0] = (av[u].x > 0.5f) ? e : e * NEG_BIG;
                s = ssrc + sd.y; e = fmaxf(s, ALPHA * s);
                v[1] = (av[u].y > 0.5f) ? e : e * NEG_BIG;
                s = ssrc + sd.z; e = fmaxf(s, ALPHA * s);
                v[2] = (av[u].z > 0.5f) ? e : e * NEG_BIG;
                s = ssrc + sd.w; e = fmaxf(s, ALPHA * s);
                v[3] = (av[u].w > 0.5f) ? e : e * NEG_BIG;
            }
            float cm = fmaxf(fmaxf(v[0], v[1]), fmaxf(v[2], v[3]));

            if (__any_sync(0xffffffffu, cm >= m)) {
                float wm = cm;
#pragma unroll
                for (int o = 16; o; o >>= 1)
                    wm = fmaxf(wm, __shfl_xor_sync(0xffffffffu, wm, o));
                if (wm > m) {           // new record: reset tie set
                    m = wm;
                    cntf = 0.0f; hacc0 = 0.0f; hacc1 = 0.0f;
                }
                // gather exact-equal ties (typically exactly 1 pop)
#pragma unroll
                for (int k = 0; k < 4; k++) {
                    unsigned bm = __ballot_sync(0xffffffffu, v[k] == m);
                    while (bm) {
                        int b = __ffs(bm) - 1;
                        bm &= bm - 1;
                        int j = j0 + u * 128 + b * 4 + k;
                        float2 hv = *(const float2*)(g_h + (size_t)j * F_OUT + lane * 2);
                        hacc0 += hv.x;
                        hacc1 += hv.y;
                        cntf  += 1.0f;
                    }
                }
            }
        }
    }

    if (m >= SAFE_M) {
        float inv = 1.0f / cntf;
        float o0 = hacc0 * inv;
        float o1 = hacc1 * inv;
        o0 = fmaxf(o0, ALPHA * o0);
        o1 = fmaxf(o1, ALPHA * o1);
        *(float2*)(out + (size_t)row * F_OUT + lane * 2) = make_float2(o0, o1);
    } else if (lane == 0) {
        g_m[row] = m;
        int idx = atomicAdd(&g_nflag, 1);
        g_flag_list[idx] = row;
    }
}

// ---------------------------------------------------------------------------
// Kernel D (pass 2): full dense softmax for the rare flagged rows (~0-3).
// One block per flagged row: stage p into smem, then 1x8192 x 8192x64 GEMV.
// ---------------------------------------------------------------------------
__global__ __launch_bounds__(256) void pass2_kernel(
    const float* __restrict__ adj, float* __restrict__ out)
{
    __shared__ float p_s[N_NODES];      // 32 KB
    __shared__ float warp_l[8];
    __shared__ float warp_acc[8][64];

    const int tid  = threadIdx.x;
    const int warp = tid >> 5;
    const int lane = tid & 31;
    const int nflag = g_nflag;

    for (int f = blockIdx.x; f < nflag; f += gridDim.x) {
        const int row = g_flag_list[f];
        const float m = g_m[row];
        const float ssrc = g_ssrc[row];
        const float* adjrow = adj + (size_t)row * N_NODES;
        const int seg = warp * 1024;

        // Phase 1: p_s[j] = exp(v_j - m), partial l
        float lpart = 0.0f;
        for (int t = 0; t < 8; t++) {
            int j = seg + t * 128 + lane * 4;
            float4 av = __ldcs((const float4*)(adjrow + j));
            float4 sd = *(const float4*)(g_sdst + j);
            float p[4];
            {
                float s, e, v;
                s = ssrc + sd.x; e = fmaxf(s, ALPHA * s);
                v = (av.x > 0.5f) ? e : e * NEG_BIG; p[0] = __expf(v - m);
                s = ssrc + sd.y; e = fmaxf(s, ALPHA * s);
                v = (av.y > 0.5f) ? e : e * NEG_BIG; p[1] = __expf(v - m);
                s = ssrc + sd.z; e = fmaxf(s, ALPHA * s);
                v = (av.z > 0.5f) ? e : e * NEG_BIG; p[2] = __expf(v - m);
                s = ssrc + sd.w; e = fmaxf(s, ALPHA * s);
                v = (av.w > 0.5f) ? e : e * NEG_BIG; p[3] = __expf(v - m);
            }
            lpart += (p[0] + p[1]) + (p[2] + p[3]);
            *(float4*)(p_s + j) = make_float4(p[0], p[1], p[2], p[3]);
        }
#pragma unroll
        for (int o = 16; o; o >>= 1)
            lpart += __shfl_xor_sync(0xffffffffu, lpart, o);
        if (lane == 0) warp_l[warp] = lpart;
        __syncthreads();

        // Phase 2: GEMV. Warp handles its 1024 j's; lane owns 2 output dims.
        float a0 = 0.0f, a1 = 0.0f;
        for (int t = 0; t < 1024; t++) {
            int j = seg + t;
            float pb = p_s[j];                      // smem broadcast
            float2 hv = *(const float2*)(g_h + (size_t)j * F_OUT + lane * 2);
            a0 += pb * hv.x;
            a1 += pb * hv.y;
        }
        warp_acc[warp][lane * 2 + 0] = a0;
        warp_acc[warp][lane * 2 + 1] = a1;
        __syncthreads();

        if (tid < 64) {
            float l = 0.0f, s = 0.0f;
#pragma unroll
            for (int w = 0; w < 8; w++) { l += warp_l[w]; s += warp_acc[w][tid]; }
            float o = s / l;
            o = fmaxf(o, ALPHA * o);
            out[(size_t)row * F_OUT + tid] = o;
        }
        __syncthreads();
    }
}

// ---------------------------------------------------------------------------
extern "C" void kernel_launch(void* const* d_in, const int* in_sizes, int n_in,
                              void* d_out, int out_size)
{
    const float* nodes = (const float*)d_in[0];   // [8192, 256]
    const float* adj   = (const float*)d_in[1];   // [8192, 8192]
    const float* W     = (const float*)d_in[2];   // [256, 64]
    const float* a     = (const float*)d_in[3];   // [128]
    float* out = (float*)d_out;                   // [8192, 64]

    gemm_h_kernel<<<N_NODES / 32, 256>>>(nodes, W);
    score_kernel<<<N_NODES / 8, 256>>>(a);
    pass1_kernel<<<N_NODES / 8, 256>>>(adj, out);
    pass2_kernel<<<16, 256>>>(adj, out);
}

// round 6
// speedup vs baseline: 5.7094x; 2.6618x over previous
#include <cuda_runtime.h>
#include <math_constants.h>

#define N_NODES 8192
#define F_IN    256
#define F_OUT   64
#define ALPHA   0.2f
#define NEG_BIG -9e15f
#define SAFE_M  1e10f   // ULP(m) >= 1024 >> 88 -> all non-ties underflow to exactly 0

// Scratch (__device__ globals: allocation-free rule)
__device__ float g_h[N_NODES * F_OUT];     // 2 MB
__device__ float g_ssrc[N_NODES];
__device__ float g_sdst[N_NODES];
__device__ float g_m[N_NODES];
__device__ int   g_flag_list[N_NODES];
__device__ int   g_nflag;
__device__ float g_acc2[N_NODES * 65];     // per-flagged-row: 64 dims + l

// ---------------------------------------------------------------------------
// Kernel A: h = nodes @ W (8192x256 @ 256x64), fused s_src/s_dst epilogue.
// Also resets g_nflag and zeroes g_acc2 (graph-replay safe).
// ---------------------------------------------------------------------------
__global__ __launch_bounds__(256) void gemm_h_kernel(
    const float* __restrict__ nodes, const float* __restrict__ W,
    const float* __restrict__ a)
{
    __shared__ float As[32][68];   // padded: avoid conflicts
    __shared__ float Bs[64][68];

    const int tid = threadIdx.x;
    const int rowBase = blockIdx.x * 32;
    const int tr = tid >> 4;       // 0..15 -> 2 rows each
    const int tc = tid & 15;       // 0..15 -> 4 cols each

    // Housekeeping for later kernels (independent of the GEMM)
    {
        int gt = blockIdx.x * 256 + tid;
        if (gt == 0) g_nflag = 0;
        for (int t = gt; t < N_NODES * 65; t += 256 * 256)
            g_acc2[t] = 0.0f;
    }

    float acc[2][4] = {};

    for (int k0 = 0; k0 < F_IN; k0 += 64) {
#pragma unroll
        for (int it = 0; it < 2; it++) {
            int idx = tid + it * 256;
            int r   = idx >> 4;
            int kq  = (idx & 15) * 4;
            float4 vv = *(const float4*)(nodes + (size_t)(rowBase + r) * F_IN + k0 + kq);
            *(float4*)(&As[r][kq]) = vv;
        }
#pragma unroll
        for (int it = 0; it < 4; it++) {
            int idx = tid + it * 256;
            int k   = idx >> 4;
            int nq  = (idx & 15) * 4;
            *(float4*)(&Bs[k][nq]) = *(const float4*)(W + (size_t)(k0 + k) * F_OUT + nq);
        }
        __syncthreads();

#pragma unroll
        for (int kk = 0; kk < 64; kk++) {
            float a0 = As[tr * 2 + 0][kk];
            float a1 = As[tr * 2 + 1][kk];
            float4 b4 = *(const float4*)(&Bs[kk][tc * 4]);
            acc[0][0] += a0 * b4.x; acc[0][1] += a0 * b4.y; acc[0][2] += a0 * b4.z; acc[0][3] += a0 * b4.w;
            acc[1][0] += a1 * b4.x; acc[1][1] += a1 * b4.y; acc[1][2] += a1 * b4.z; acc[1][3] += a1 * b4.w;
        }
        __syncthreads();
    }

#pragma unroll
    for (int rr = 0; rr < 2; rr++) {
        float4 o = make_float4(acc[rr][0], acc[rr][1], acc[rr][2], acc[rr][3]);
        *(float4*)(g_h + (size_t)(rowBase + tr * 2 + rr) * F_OUT + tc * 4) = o;
    }

    // Fused score epilogue: ssrc = h . a[:64], sdst = h . a[64:]
    float4 Asv = *(const float4*)(a + tc * 4);
    float4 Adv = *(const float4*)(a + F_OUT + tc * 4);
#pragma unroll
    for (int rr = 0; rr < 2; rr++) {
        float ps = acc[rr][0] * Asv.x + acc[rr][1] * Asv.y + acc[rr][2] * Asv.z + acc[rr][3] * Asv.w;
        float pd = acc[rr][0] * Adv.x + acc[rr][1] * Adv.y + acc[rr][2] * Adv.z + acc[rr][3] * Adv.w;
#pragma unroll
        for (int o = 1; o < 16; o <<= 1) {
            ps += __shfl_xor_sync(0xffffffffu, ps, o);
            pd += __shfl_xor_sync(0xffffffffu, pd, o);
        }
        if (tc == 0) {
            int row = rowBase + tr * 2 + rr;
            g_ssrc[row] = ps;
            g_sdst[row] = pd;
        }
    }
}

// ---------------------------------------------------------------------------
// Kernel C (pass 1): stream adj once. Running max + exact-tie gather.
// If final m >= SAFE_M: exp(v-m) is exactly {1 for ties, 0 otherwise} in fp32,
// so out = leaky(mean(h over ties)). Else: flag row for dense pass 2.
// ---------------------------------------------------------------------------
__global__ __launch_bounds__(256) void pass1_kernel(
    const float* __restrict__ adj, float* __restrict__ out)
{
    __shared__ float sdst_s[N_NODES];   // 32 KB
    for (int t = threadIdx.x; t < N_NODES / 4; t += 256)
        ((float4*)sdst_s)[t] = ((const float4*)g_sdst)[t];
    __syncthreads();

    const int warp = threadIdx.x >> 5;
    const int lane = threadIdx.x & 31;
    const int row  = blockIdx.x * 8 + warp;

    const float ssrc = g_ssrc[row];
    const float* adjrow = adj + (size_t)row * N_NODES;

    float m = -CUDART_INF_F;
    float cntf = 0.0f;
    float hacc0 = 0.0f, hacc1 = 0.0f;   // lane owns dims 2*lane, 2*lane+1

    for (int j0 = 0; j0 < N_NODES; j0 += 512) {
        float4 av[4];
#pragma unroll
        for (int u = 0; u < 4; u++)
            av[u] = __ldcs((const float4*)(adjrow + j0 + u * 128) + lane);

#pragma unroll
        for (int u = 0; u < 4; u++) {
            const int jc = j0 + u * 128 + lane * 4;
            float4 sd = *(const float4*)(sdst_s + jc);

            float v[4];
            {
                float s, e;
                s = ssrc + sd.x; e = fmaxf(s, ALPHA * s);
                v[0] = (av[u].x > 0.5f) ? e : e * NEG_BIG;
                s = ssrc + sd.y; e = fmaxf(s, ALPHA * s);
                v[1] = (av[u].y > 0.5f) ? e : e * NEG_BIG;
                s = ssrc + sd.z; e = fmaxf(s, ALPHA * s);
                v[2] = (av[u].z > 0.5f) ? e : e * NEG_BIG;
                s = ssrc + sd.w; e = fmaxf(s, ALPHA * s);
                v[3] = (av[u].w > 0.5f) ? e : e * NEG_BIG;
            }
            float cm = fmaxf(fmaxf(v[0], v[1]), fmaxf(v[2], v[3]));

            if (__any_sync(0xffffffffu, cm >= m)) {
                float wm = cm;
#pragma unroll
                for (int o = 16; o; o >>= 1)
                    wm = fmaxf(wm, __shfl_xor_sync(0xffffffffu, wm, o));
                if (wm > m) {           // new record: reset tie set
                    m = wm;
                    cntf = 0.0f; hacc0 = 0.0f; hacc1 = 0.0f;
                }
#pragma unroll
                for (int k = 0; k < 4; k++) {
                    unsigned bm = __ballot_sync(0xffffffffu, v[k] == m);
                    while (bm) {
                        int b = __ffs(bm) - 1;
                        bm &= bm - 1;
                        int j = j0 + u * 128 + b * 4 + k;
                        float2 hv = *(const float2*)(g_h + (size_t)j * F_OUT + lane * 2);
                        hacc0 += hv.x;
                        hacc1 += hv.y;
                        cntf  += 1.0f;
                    }
                }
            }
        }
    }

    if (m >= SAFE_M) {
        float inv = 1.0f / cntf;
        float o0 = hacc0 * inv;
        float o1 = hacc1 * inv;
        o0 = fmaxf(o0, ALPHA * o0);
        o1 = fmaxf(o1, ALPHA * o1);
        *(float2*)(out + (size_t)row * F_OUT + lane * 2) = make_float2(o0, o1);
    } else if (lane == 0) {
        g_m[row] = m;
        int idx = atomicAdd(&g_nflag, 1);
        g_flag_list[idx] = row;
    }
}

// ---------------------------------------------------------------------------
// Kernel D (pass 2a): dense softmax partials for flagged rows, spread wide.
// Work item w covers (flag f = w/64, j-chunk = (w%64)*128). Block layout:
// d = tid&63 (coalesced h reads), jl = tid>>6 (4 j-lanes, 32 j's each).
// Accumulates Sum(p*h[:,d]) and Sum(p) into g_acc2 via atomics.
// ---------------------------------------------------------------------------
__global__ __launch_bounds__(256) void pass2a_kernel(const float* __restrict__ adj)
{
    const int nflag = g_nflag;
    if (nflag == 0) return;
    const int tid = threadIdx.x;
    const int d   = tid & 63;
    const int jl  = tid >> 6;          // 0..3
    const int total = nflag * 64;

    for (int w = blockIdx.x; w < total; w += gridDim.x) {
        const int f    = w >> 6;
        const int row  = g_flag_list[f];
        const float m  = g_m[row];
        const float ssrc = g_ssrc[row];
        const int j0   = (w & 63) * 128;
        const float* adjrow = adj + (size_t)row * N_NODES + j0;

        float acc = 0.0f;
        float lsum = 0.0f;
#pragma unroll 8
        for (int t = 0; t < 32; t++) {
            int j = jl + t * 4;                    // 0..127, stride 4
            float av = __ldg(adjrow + j);          // warp-uniform -> broadcast
            float s = ssrc + g_sdst[j0 + j];
            float e = fmaxf(s, ALPHA * s);
            float v = (av > 0.5f) ? e : e * NEG_BIG;
            float p = __expf(v - m);               // <=1 (m is true row max)
            acc += p * g_h[(size_t)(j0 + j) * F_OUT + d];
            if (d == 0) lsum += p;
        }
        atomicAdd(&g_acc2[f * 65 + d], acc);
        if (d == 0) atomicAdd(&g_acc2[f * 65 + 64], lsum);
    }
}

// ---------------------------------------------------------------------------
// Kernel E (pass 2b): normalize flagged rows.
// ---------------------------------------------------------------------------
__global__ __launch_bounds__(64) void pass2b_kernel(float* __restrict__ out)
{
    const int nflag = g_nflag;
    const int d = threadIdx.x;         // 0..63
    for (int f = blockIdx.x; f < nflag; f += gridDim.x) {
        const int row = g_flag_list[f];
        float l = g_acc2[f * 65 + 64];
        float o = g_acc2[f * 65 + d] / l;
        o = fmaxf(o, ALPHA * o);
        out[(size_t)row * F_OUT + d] = o;
    }
}

// ---------------------------------------------------------------------------
extern "C" void kernel_launch(void* const* d_in, const int* in_sizes, int n_in,
                              void* d_out, int out_size)
{
    const float* nodes = (const float*)d_in[0];   // [8192, 256]
    const float* adj   = (const float*)d_in[1];   // [8192, 8192]
    const float* W     = (const float*)d_in[2];   // [256, 64]
    const float* a     = (const float*)d_in[3];   // [128]
    float* out = (float*)d_out;                   // [8192, 64]

    gemm_h_kernel<<<N_NODES / 32, 256>>>(nodes, W, a);
    pass1_kernel<<<N_NODES / 8, 256>>>(adj, out);
    pass2a_kernel<<<2048, 256>>>(adj);
    pass2b_kernel<<<64, 64>>>(out);
}